// round 13
// baseline (speedup 1.0000x reference)
#include <cuda_runtime.h>
#include <cuda_bf16.h>
#include <math.h>
#include <stdint.h>

#define N_TOK 2048
#define DM    1024
#define NH    16
#define DH    64
#define CHK   128
#define NCK   16
#define NLVL  4
#define NVAR  5
#define S1 ((size_t)N_TOK*DM)
#define DMDM ((size_t)DM*DM)

typedef unsigned long long ull;

__device__ float g_scratch[67108864];  // 256 MB scratch

#define OFF_Q     ((size_t)0)
#define OFF_K     (1*S1)
#define OFF_V     (2*S1)
#define OFF_KL    (3*S1)
#define OFF_VL    (4*S1)
#define OFF_QP    (5*S1)
#define OFF_KP    (6*S1)
#define OFF_VX    (11*S1)
#define OFF_WB    (16*S1)
#define OFF_OLA   (18*S1)
#define OFF_AB    (21*S1)
#define OFF_LOC   (23*S1)
#define OFF_GLOB  (24*S1)
#define OFF_XDB   (25*S1)
#define OFF_GH    (27*S1)
#define OFF_MIX   (28*S1)
#define OFF_CKV   (29*S1)
#define OFF_CK    (OFF_CKV + (size_t)NVAR*NH*NCK*DH*DH)
#define OFF_ALPHA (OFF_CK + (size_t)NVAR*NH*NCK*DH)

__device__ __forceinline__ float phi_f(float x){ return x > 0.f ? x + 1.f : expf(x); }

// ---------- f32x2 packed math ----------
__device__ __forceinline__ ull pk2(float lo, float hi){
    ull r; asm("mov.b64 %0, {%1,%2};" : "=l"(r) : "f"(lo), "f"(hi)); return r;
}
__device__ __forceinline__ void upk2(ull v, float& lo, float& hi){
    asm("mov.b64 {%0,%1}, %2;" : "=f"(lo), "=f"(hi) : "l"(v));
}
__device__ __forceinline__ void fma2(ull& d, ull a, ull b){
    asm("fma.rn.f32x2 %0, %1, %2, %0;" : "+l"(d) : "l"(a), "l"(b));
}

__device__ __forceinline__ uint32_t smem_u32addr(const void* p){
    uint32_t a;
    asm("{ .reg .u64 t; cvta.to.shared.u64 t, %1; cvt.u32.u64 %0, t; }" : "=r"(a) : "l"(p));
    return a;
}
__device__ __forceinline__ void cp_async16(uint32_t saddr, const void* gptr){
    asm volatile("cp.async.cg.shared.global [%0], [%1], 16;" :: "r"(saddr), "l"(gptr));
}

// ===================== f32 -> bf16 hi/lo split =====================
__global__ void conv_bf16(const float* __restrict__ in, __nv_bfloat16* __restrict__ hi,
                          __nv_bfloat16* __restrict__ lo, size_t n)
{
    for (size_t i = (size_t)blockIdx.x*blockDim.x + threadIdx.x; i < n;
         i += (size_t)gridDim.x*blockDim.x){
        float x = in[i];
        __nv_bfloat16 h = __float2bfloat16(x);
        hi[i] = h;
        lo[i] = __float2bfloat16(x - __bfloat162float(h));
    }
}

struct CW { const float* src[5]; };
__global__ void conv_w5(CW cw, __nv_bfloat16* __restrict__ base)
{
    const float* __restrict__ in = cw.src[blockIdx.z];
    __nv_bfloat16* hi = base + (size_t)blockIdx.z*2*DMDM;
    __nv_bfloat16* lo = hi + DMDM;
    for (size_t i = (size_t)blockIdx.x*blockDim.x + threadIdx.x; i < DMDM;
         i += (size_t)gridDim.x*blockDim.x){
        float x = in[i];
        __nv_bfloat16 h = __float2bfloat16(x);
        hi[i] = h;
        lo[i] = __float2bfloat16(x - __bfloat162float(h));
    }
}

// ===================== bf16 split tensor-core GEMM (3-stage cp.async, 2 CTAs/SM) =====================
// per-slot secondary output Y2 with code: 0=none, 2=phi(Y), 3=copy(Y)
struct PB {
    const __nv_bfloat16* Wh[5];
    const __nv_bfloat16* Wl[5];
    const float* b[5];
    float*       Y[5];
    float*       Y2[5];
    int          c2[5];
};

__device__ __forceinline__ void mma_bf16(float* d, const uint32_t* a, const uint32_t* b){
    asm("mma.sync.aligned.m16n8k16.row.col.f32.bf16.bf16.f32 "
        "{%0,%1,%2,%3}, {%4,%5,%6,%7}, {%8,%9}, {%0,%1,%2,%3};"
        : "+f"(d[0]),"+f"(d[1]),"+f"(d[2]),"+f"(d[3])
        : "r"(a[0]),"r"(a[1]),"r"(a[2]),"r"(a[3]),
          "r"(b[0]),"r"(b[1]));
}

#define GS_ROW 12
#define GS_MAT (128*GS_ROW)
#define GS_STAGE (2*GS_MAT)
#define GSTAGES 3
#define GS_HALF (GSTAGES*GS_STAGE)
#define GEMM_SMEM_BYTES (2*GS_HALF*4)       // 73728

__global__ __launch_bounds__(256, 2)
void gemm_bf16(const __nv_bfloat16* __restrict__ Ah, const __nv_bfloat16* __restrict__ Al,
               int lda, PB p, int ldw, int ldy, int K, int act)
{
    extern __shared__ uint32_t gsm[];
    uint32_t* SA = gsm;
    uint32_t* SB = gsm + GS_HALF;

    const __nv_bfloat16* __restrict__ Wh = p.Wh[blockIdx.z];
    const __nv_bfloat16* __restrict__ Wl = p.Wl[blockIdx.z];
    const float* __restrict__ bias       = p.b[blockIdx.z];
    float* __restrict__ Y                = p.Y[blockIdx.z];
    float* __restrict__ Y2               = p.Y2[blockIdx.z];
    const int code                       = p.c2[blockIdx.z];

    const int tid  = threadIdx.x;
    const int lane = tid & 31;
    const int warp = tid >> 5;
    const int wm = warp >> 2;
    const int wn = warp & 3;
    const int g  = lane >> 2;
    const int t4 = lane & 3;
    const int m0 = blockIdx.y * 128, n0 = blockIdx.x * 128;

    const int r   = tid >> 1;
    const int ch  = tid & 1;
    const int c8  = ch * 8;

    const uint32_t sA = smem_u32addr(SA);
    const uint32_t sB = smem_u32addr(SB);

    float acc[4][4][4] = {};

    auto issue = [&](int st, int k0){
        const size_t ao = (size_t)(m0 + r)*lda + k0 + c8;
        const size_t bo = (size_t)(n0 + r)*ldw + k0 + c8;
        uint32_t off = ((uint32_t)st*GS_STAGE + (uint32_t)r*GS_ROW + ch*4)*4;
        cp_async16(sA + off,              Ah + ao);
        cp_async16(sA + off + GS_MAT*4,   Al + ao);
        cp_async16(sB + off,              Wh + bo);
        cp_async16(sB + off + GS_MAT*4,   Wl + bo);
    };

    const int nsteps = K >> 4;
    issue(0, 0);
    asm volatile("cp.async.commit_group;");
    issue(1, 16);
    asm volatile("cp.async.commit_group;");

    for (int s = 0; s < nsteps; s++){
        const bool more2 = (s + 2 < nsteps);
        if (more2) asm volatile("cp.async.wait_group 1;");
        else       asm volatile("cp.async.wait_group 0;");
        __syncthreads();
        const int st = s % GSTAGES;
        if (more2){
            issue((s + 2) % GSTAGES, (s + 2) * 16);
            asm volatile("cp.async.commit_group;");
        }
        const uint32_t* Acur = SA + st*GS_STAGE;
        const uint32_t* Bcur = SB + st*GS_STAGE;
        uint32_t bh[4][2], bl[4][2];
        #pragma unroll
        for (int j = 0; j < 4; j++){
            int nb = wn*32 + j*8 + g;
            bh[j][0] = Bcur[nb*GS_ROW + t4];
            bh[j][1] = Bcur[nb*GS_ROW + t4 + 4];
            bl[j][0] = Bcur[GS_MAT + nb*GS_ROW + t4];
            bl[j][1] = Bcur[GS_MAT + nb*GS_ROW + t4 + 4];
        }
        #pragma unroll
        for (int i = 0; i < 4; i++){
            int mb = wm*64 + i*16 + g;
            uint32_t a_h[4], a_l[4];
            a_h[0] = Acur[mb*GS_ROW + t4];
            a_h[1] = Acur[(mb+8)*GS_ROW + t4];
            a_h[2] = Acur[mb*GS_ROW + t4 + 4];
            a_h[3] = Acur[(mb+8)*GS_ROW + t4 + 4];
            a_l[0] = Acur[GS_MAT + mb*GS_ROW + t4];
            a_l[1] = Acur[GS_MAT + (mb+8)*GS_ROW + t4];
            a_l[2] = Acur[GS_MAT + mb*GS_ROW + t4 + 4];
            a_l[3] = Acur[GS_MAT + (mb+8)*GS_ROW + t4 + 4];
            #pragma unroll
            for (int j = 0; j < 4; j++){
                mma_bf16(acc[i][j], a_h, bh[j]);
                mma_bf16(acc[i][j], a_h, bl[j]);
                mma_bf16(acc[i][j], a_l, bh[j]);
            }
        }
        __syncthreads();
    }

    #pragma unroll
    for (int i = 0; i < 4; i++){
        int mrow = m0 + wm*64 + i*16 + g;
        #pragma unroll
        for (int j = 0; j < 4; j++){
            int ncol = n0 + wn*32 + j*8 + 2*t4;
            float v0 = acc[i][j][0], v1 = acc[i][j][1];
            float v2 = acc[i][j][2], v3 = acc[i][j][3];
            if (bias){
                float b0 = bias[ncol], b1 = bias[ncol+1];
                v0 += b0; v1 += b1; v2 += b0; v3 += b1;
            }
            if (act == 1){
                v0 = v0/(1.f+expf(-v0)); v1 = v1/(1.f+expf(-v1));
                v2 = v2/(1.f+expf(-v2)); v3 = v3/(1.f+expf(-v3));
            }
            float2 o01; o01.x = v0; o01.y = v1;
            float2 o23; o23.x = v2; o23.y = v3;
            *reinterpret_cast<float2*>(&Y[(size_t)mrow*ldy + ncol])     = o01;
            *reinterpret_cast<float2*>(&Y[(size_t)(mrow+8)*ldy + ncol]) = o23;
            if (code){
                float w0=v0, w1=v1, w2=v2, w3=v3;
                if (code == 2){ w0=phi_f(v0); w1=phi_f(v1); w2=phi_f(v2); w3=phi_f(v3); }
                float2 p01; p01.x = w0; p01.y = w1;
                float2 p23; p23.x = w2; p23.y = w3;
                *reinterpret_cast<float2*>(&Y2[(size_t)mrow*ldy + ncol])     = p01;
                *reinterpret_cast<float2*>(&Y2[(size_t)(mrow+8)*ldy + ncol]) = p23;
            }
        }
    }
}

// ===================== fused haar transform + causal blockmean + phi =====================
__global__ void haar_fused(const float* __restrict__ Kin, const float* __restrict__ Vin,
                           const float* __restrict__ hWk, const float* __restrict__ hWv,
                           float* __restrict__ kd_base, float* __restrict__ vd_base)
{
    __shared__ __align__(16) float As[16][68];
    __shared__ __align__(16) float Ws[16][68];
    __shared__ __align__(16) float Ys[64][68];
    const int z = blockIdx.z;
    const int lvl = z >> 5;
    const int h  = (z >> 1) & 15;
    const int kv = z & 1;
    const int blkm = 2 << lvl;
    const float* A = (kv ? Vin : Kin) + h*DH;
    const float* W = (kv ? hWv : hWk) + (size_t)lvl*DH*DH;
    float* Yout = (kv ? vd_base : kd_base) + (size_t)(lvl+1)*S1 + h*DH;
    const int t  = threadIdx.x;
    const int tx = t & 15, ty = t >> 4;
    const int m0 = blockIdx.y * 64;
    const int lrow = t >> 2;
    const int lk   = (t & 3) * 4;
    float acc[4][4] = {};
    for (int k0 = 0; k0 < DH; k0 += 16) {
        float4 av = *reinterpret_cast<const float4*>(&A[(size_t)(m0 + lrow)*DM + k0 + lk]);
        float4 wv = *reinterpret_cast<const float4*>(&W[(size_t)lrow*DH + k0 + lk]);
        As[lk+0][lrow]=av.x; As[lk+1][lrow]=av.y; As[lk+2][lrow]=av.z; As[lk+3][lrow]=av.w;
        Ws[lk+0][lrow]=wv.x; Ws[lk+1][lrow]=wv.y; Ws[lk+2][lrow]=wv.z; Ws[lk+3][lrow]=wv.w;
        __syncthreads();
        #pragma unroll
        for (int kk = 0; kk < 16; kk++) {
            float4 a = *reinterpret_cast<float4*>(&As[kk][ty*4]);
            float4 b = *reinterpret_cast<float4*>(&Ws[kk][tx*4]);
            float aa[4] = {a.x,a.y,a.z,a.w};
            float bb[4] = {b.x,b.y,b.z,b.w};
            #pragma unroll
            for (int i=0;i<4;i++)
                #pragma unroll
                for (int j=0;j<4;j++)
                    acc[i][j] += aa[i]*bb[j];
        }
        __syncthreads();
    }
    #pragma unroll
    for (int i=0;i<4;i++){
        float4 o; o.x=acc[i][0]; o.y=acc[i][1]; o.z=acc[i][2]; o.w=acc[i][3];
        *reinterpret_cast<float4*>(&Ys[ty*4+i][tx*4]) = o;
    }
    __syncthreads();
    {
        const int c = t & 63;
        const int r0 = (t >> 6) * 16;
        const int mask = blkm - 1;
        float run = 0.f;
        #pragma unroll
        for (int rr = 0; rr < 16; rr++){
            int m = r0 + rr;
            if ((m & mask) == 0) run = 0.f;
            run += Ys[m][c];
            float inv = 1.0f / (float)((m & mask) + 1);
            float val = run * inv;
            if (!kv) val = phi_f(val);
            Yout[(size_t)(m0 + m)*DM + c] = val;
        }
    }
}

// phase A: ckv = Kc^T Vc, ck = colsum(Kc)  (f32x2 inner loop)
__global__ void chunk_kv(const float* __restrict__ kp, const float* __restrict__ vx,
                         float* __restrict__ ckv, float* __restrict__ ck)
{
    __shared__ __align__(16) float Ks[16][68], Vs[16][68];
    const int c = blockIdx.x, h = blockIdx.y, vv = blockIdx.z;
    const int t = threadIdx.x, tx = t & 15, ty = t >> 4;
    const float* kb = kp + (size_t)vv*S1;
    const float* vb = vx + (size_t)vv*S1;
    const size_t rowbase = (size_t)c*CHK*DM + (size_t)h*DH;
    const int lr = t >> 4, lc = (t & 15) * 4;
    ull acc2[4][2] = {};
    for (int k0 = 0; k0 < CHK; k0 += 16){
        float4 a = *reinterpret_cast<const float4*>(&kb[rowbase + (size_t)(k0+lr)*DM + lc]);
        float4 b = *reinterpret_cast<const float4*>(&vb[rowbase + (size_t)(k0+lr)*DM + lc]);
        Ks[lr][lc+0]=a.x; Ks[lr][lc+1]=a.y; Ks[lr][lc+2]=a.z; Ks[lr][lc+3]=a.w;
        Vs[lr][lc+0]=b.x; Vs[lr][lc+1]=b.y; Vs[lr][lc+2]=b.z; Vs[lr][lc+3]=b.w;
        __syncthreads();
        #pragma unroll
        for (int kk = 0; kk < 16; kk++){
            float4 a4 = *reinterpret_cast<float4*>(&Ks[kk][ty*4]);
            ull b2a = *reinterpret_cast<ull*>(&Vs[kk][tx*4]);
            ull b2b = *reinterpret_cast<ull*>(&Vs[kk][tx*4+2]);
            float aa[4]={a4.x,a4.y,a4.z,a4.w};
            #pragma unroll
            for (int i=0;i<4;i++){
                ull ai = pk2(aa[i], aa[i]);
                fma2(acc2[i][0], ai, b2a);
                fma2(acc2[i][1], ai, b2b);
            }
        }
        __syncthreads();
    }
    float* outm = ckv + (((size_t)vv*NH + h)*NCK + c)*((size_t)DH*DH);
    #pragma unroll
    for (int i=0;i<4;i++){
        float o0,o1,o2,o3;
        upk2(acc2[i][0], o0, o1);
        upk2(acc2[i][1], o2, o3);
        float4 o; o.x=o0; o.y=o1; o.z=o2; o.w=o3;
        *reinterpret_cast<float4*>(&outm[(size_t)(ty*4+i)*DH + tx*4]) = o;
    }
    if (t < DH){
        float s = 0.f;
        for (int r = 0; r < CHK; r++) s += kb[rowbase + (size_t)r*DM + t];
        ck[(((size_t)vv*NH + h)*NCK + c)*DH + t] = s;
    }
}

// phase B: exclusive prefix over chunks
__global__ void prefix_scan(float* __restrict__ ckv, float* __restrict__ ck)
{
    const int h = blockIdx.x, vv = blockIdx.y, t = threadIdx.x;
    const size_t base = (((size_t)vv*NH + h)*NCK) * (size_t)(DH*DH);
    for (int u = t; u < DH*DH; u += 256){
        float run = 0.f;
        for (int c = 0; c < NCK; c++){
            size_t idx = base + (size_t)c*DH*DH + u;
            float tmp = ckv[idx]; ckv[idx] = run; run += tmp;
        }
    }
    if (t < DH){
        const size_t b2 = (((size_t)vv*NH + h)*NCK) * (size_t)DH;
        float run = 0.f;
        for (int c = 0; c < NCK; c++){
            size_t idx = b2 + (size_t)c*DH + t;
            float tmp = ck[idx]; ck[idx] = run; run += tmp;
        }
    }
}

// phase C with f32x2 packed FMA
#define LA_SMEM_FLOATS (64*132 + 128*68 + 128*132 + 64*68 + 64 + 128)
#define LA_SMEM_BYTES  (LA_SMEM_FLOATS*4)
__global__ void linatt(const float* __restrict__ qp, const float* __restrict__ kp,
                       const float* __restrict__ vx, const float* __restrict__ ckv,
                       const float* __restrict__ ck, float* __restrict__ ola)
{
    extern __shared__ float sm[];
    const int c = blockIdx.x, h = blockIdx.y, vv = blockIdx.z;
    const int t = threadIdx.x, tx = t & 15, ty = t >> 4;
    float* Qt   = sm;
    float* KVu  = Qt + 64*132;
    float* Ss   = KVu + 128*68;
    float* SKVs = Ss + 128*132;
    float* SKs  = SKVs + 64*68;
    float* nrm  = SKs + 64;
    const float* kb = kp + (size_t)vv*S1;
    const float* vb = vx + (size_t)vv*S1;
    const size_t rowbase = (size_t)c*CHK*DM + (size_t)h*DH;
    {
        int d = t & 63;
        for (int g = t >> 6; g < CHK; g += 4){
            Qt[d*132 + g]  = qp[rowbase + (size_t)g*DM + d];
            KVu[d*132 + g] = kb[rowbase + (size_t)g*DM + d];
        }
    }
    __syncthreads();
    {
        ull acc2[8][4] = {};
        #pragma unroll 2
        for (int d = 0; d < DH; d++){
            float4 a0 = *reinterpret_cast<float4*>(&Qt[d*132 + ty*8]);
            float4 a1 = *reinterpret_cast<float4*>(&Qt[d*132 + ty*8 + 4]);
            float qa[8]={a0.x,a0.y,a0.z,a0.w,a1.x,a1.y,a1.z,a1.w};
            ull qa2[8];
            #pragma unroll
            for (int i=0;i<8;i++) qa2[i] = pk2(qa[i], qa[i]);
            ull kv2[4];
            #pragma unroll
            for (int j2=0;j2<4;j2++)
                kv2[j2] = *reinterpret_cast<ull*>(&KVu[d*132 + tx*8 + 2*j2]);
            #pragma unroll
            for (int i=0;i<8;i++)
                #pragma unroll
                for (int j2=0;j2<4;j2++)
                    fma2(acc2[i][j2], qa2[i], kv2[j2]);
        }
        #pragma unroll
        for (int i=0;i<8;i++){
            int gi = ty*8+i;
            #pragma unroll
            for (int j2=0;j2<4;j2++){
                float slo, shi; upk2(acc2[i][j2], slo, shi);
                int gj = tx*8 + 2*j2;
                float2 st;
                st.x = (gj   <= gi) ? slo : 0.0f;
                st.y = (gj+1 <= gi) ? shi : 0.0f;
                *reinterpret_cast<float2*>(&Ss[gi*132+gj]) = st;
            }
        }
    }
    __syncthreads();
    {
        int d = t & 63;
        for (int g = t >> 6; g < CHK; g += 4)
            KVu[g*68 + d] = vb[rowbase + (size_t)g*DM + d];
        const float* mc = ckv + (((size_t)vv*NH + h)*NCK + c)*((size_t)DH*DH);
        for (int u = t; u < DH*DH; u += 256)
            SKVs[(u>>6)*68 + (u&63)] = mc[u];
        if (t < DH) SKs[t] = ck[(((size_t)vv*NH + h)*NCK + c)*DH + t];
    }
    __syncthreads();
    if (t < CHK){
        float s = 0.f;
        for (int j = 0; j < CHK; j++) s += Ss[t*132 + j];
        float s2 = 0.f;
        for (int d = 0; d < DH; d++) s2 += Qt[d*132 + t]*SKs[d];
        nrm[t] = fmaxf(s + s2, 1e-6f);
    }
    __syncthreads();
    ull outv2[8][2] = {};
    #pragma unroll 2
    for (int d = 0; d < DH; d++){
        float4 a0 = *reinterpret_cast<float4*>(&Qt[d*132 + ty*8]);
        float4 a1 = *reinterpret_cast<float4*>(&Qt[d*132 + ty*8 + 4]);
        float qa[8]={a0.x,a0.y,a0.z,a0.w,a1.x,a1.y,a1.z,a1.w};
        ull qa2[8];
        #pragma unroll
        for (int i=0;i<8;i++) qa2[i] = pk2(qa[i], qa[i]);
        ull bb2[2];
        bb2[0] = *reinterpret_cast<ull*>(&SKVs[d*68 + tx*4]);
        bb2[1] = *reinterpret_cast<ull*>(&SKVs[d*68 + tx*4 + 2]);
        #pragma unroll
        for (int i=0;i<8;i++){
            fma2(outv2[i][0], qa2[i], bb2[0]);
            fma2(outv2[i][1], qa2[i], bb2[1]);
        }
    }
    #pragma unroll 2
    for (int kk = 0; kk < CHK; kk++){
        ull vb2[2];
        vb2[0] = *reinterpret_cast<ull*>(&KVu[kk*68 + tx*4]);
        vb2[1] = *reinterpret_cast<ull*>(&KVu[kk*68 + tx*4 + 2]);
        #pragma unroll
        for (int i=0;i<8;i++){
            float sv = Ss[(ty*8+i)*132 + kk];
            ull sv2 = pk2(sv, sv);
            fma2(outv2[i][0], sv2, vb2[0]);
            fma2(outv2[i][1], sv2, vb2[1]);
        }
    }
    float* ob = ola + (size_t)vv*S1;
    #pragma unroll
    for (int i=0;i<8;i++){
        int gi = ty*8+i;
        float inv = 1.0f / nrm[gi];
        float o0,o1,o2,o3;
        upk2(outv2[i][0], o0, o1);
        upk2(outv2[i][1], o2, o3);
        float4 o; o.x=o0*inv; o.y=o1*inv; o.z=o2*inv; o.w=o3*inv;
        *reinterpret_cast<float4*>(&ob[(size_t)(c*CHK+gi)*DM + h*DH + tx*4]) = o;
    }
}

// local windowed attention (window 64, causal): 128 threads, 2 per query (dim-split).
// NOTE: pair-scoped shuffle mask — the two lanes of a pair share nj, so the
// 2-lane shuffle is always convergent (full-warp mask would deadlock: nj varies per lane).
#define LOCAL_SMEM_BYTES ((2*128*68 + 64*65)*4)
__global__ void local_attn(const float* __restrict__ q, const float* __restrict__ kl,
                           const float* __restrict__ vl, float* __restrict__ outp)
{
    extern __shared__ float sm[];
    float* kT  = sm;                // [128][68]
    float* vT  = sm + 128*68;       // [128][68]
    float* scS = sm + 2*128*68;     // [64][65]
    const int h = blockIdx.y;
    const int qstart = blockIdx.x * 64;
    const int tid = threadIdx.x;    // 0..127
    const int qq   = tid >> 1;      // query 0..63
    const int half = tid & 1;       // dim half
    const int lane = tid & 31;
    const unsigned pmask = 0x3u << (lane & ~1);   // 2-lane pair mask
    for (int idx = tid; idx < 128*64; idx += 128){
        int g = idx >> 6, d = idx & 63;
        int gk = qstart - 64 + g;
        float kv = 0.f, vv = 0.f;
        if (gk >= 0){
            kv = kl[(size_t)gk*DM + h*DH + d];
            vv = vl[(size_t)gk*DM + h*DH + d];
        }
        kT[g*68 + d] = kv;
        vT[g*68 + d] = vv;
    }
    __syncthreads();
    const int i = qstart + qq;
    const int dbase = half*32;
    ull qr2[16];
    #pragma unroll
    for (int d2 = 0; d2 < 16; d2++)
        qr2[d2] = *reinterpret_cast<const ull*>(&q[(size_t)i*DM + h*DH + dbase + 2*d2]);
    const float scale = 0.125f;
    int nj = min(64, i + 1);
    float m = -1e30f;
    for (int j = 0; j < nj; j++){
        int r = qq - j + 64;
        ull sa=0, sb=0;
        #pragma unroll
        for (int d2 = 0; d2 < 16; d2 += 2){
            fma2(sa, qr2[d2  ], *reinterpret_cast<ull*>(&kT[r*68 + dbase + 2*d2    ]));
            fma2(sb, qr2[d2+1], *reinterpret_cast<ull*>(&kT[r*68 + dbase + 2*d2 + 2]));
        }
        float a0,a1,b0,b1;
        upk2(sa,a0,a1); upk2(sb,b0,b1);
        float s = (a0+a1)+(b0+b1);
        s += __shfl_xor_sync(pmask, s, 1);          // combine halves within the pair
        scS[qq*65 + j] = s;                          // both halves write same value
        m = fmaxf(m, s*scale);
    }
    float l = 0.f;
    ull accv2[16] = {};
    for (int j = 0; j < nj; j++){
        int r = qq - j + 64;
        float w = expf(scS[qq*65 + j]*scale - m);
        l += w;
        ull w2 = pk2(w, w);
        #pragma unroll
        for (int e2 = 0; e2 < 16; e2++)
            fma2(accv2[e2], w2, *reinterpret_cast<ull*>(&vT[r*68 + dbase + 2*e2]));
    }
    float inv = 1.f / l;
    #pragma unroll
    for (int e2 = 0; e2 < 16; e2++){
        float lo, hi; upk2(accv2[e2], lo, hi);
        float2 o; o.x = lo*inv; o.y = hi*inv;
        *reinterpret_cast<float2*>(&outp[(size_t)i*DM + h*DH + dbase + 2*e2]) = o;
    }
}

// glob + xd (bf16 hi/lo, own region — no aliasing)
__global__ void combine(const float* __restrict__ x, const float* __restrict__ hsc,
                        const float* __restrict__ ola, const float* __restrict__ loc,
                        float* __restrict__ glob,
                        __nv_bfloat16* __restrict__ xdh, __nv_bfloat16* __restrict__ xdl)
{
    size_t i = (size_t)blockIdx.x*blockDim.x + threadIdx.x;
    if (i >= S1) return;
    float hs[NLVL], m = -1e30f;
    #pragma unroll
    for (int l = 0; l < NLVL; l++){ hs[l] = hsc[l]; m = fmaxf(m, hs[l]); }
    float ssum = 0.f, w[NLVL];
    #pragma unroll
    for (int l = 0; l < NLVL; l++){ w[l] = expf(hs[l]-m); ssum += w[l]; }
    float inv = 1.f/ssum;
    float g = ola[i];
    #pragma unroll
    for (int l = 0; l < NLVL; l++) g += (w[l]*inv) * ola[(size_t)(l+1)*S1 + i];
    glob[i] = g;
    size_t n = i >> 10, d = i & 1023;
    float v1 = x[i];
    __nv_bfloat16 h1 = __float2bfloat16(v1);
    xdh[n*2048 + d] = h1;
    xdl[n*2048 + d] = __float2bfloat16(v1 - __bfloat162float(h1));
    float v2 = loc[i] - g;
    __nv_bfloat16 h2 = __float2bfloat16(v2);
    xdh[n*2048 + 1024 + d] = h2;
    xdl[n*2048 + 1024 + d] = __float2bfloat16(v2 - __bfloat162float(h2));
}

__global__ void alpha_k(const float* __restrict__ gh, const float* __restrict__ Wgo,
                        const float* __restrict__ bgo, float* __restrict__ alpha)
{
    int warp = threadIdx.x >> 5, lane = threadIdx.x & 31;
    int row = blockIdx.x*8 + warp;
    if (row >= N_TOK) return;
    float s = 0.f;
    for (int kk = lane; kk < DM; kk += 32) s += gh[(size_t)row*DM + kk]*Wgo[kk];
    #pragma unroll
    for (int o = 16; o; o >>= 1) s += __shfl_xor_sync(0xffffffffu, s, o);
    if (lane == 0) alpha[row] = 1.f/(1.f + expf(-(s + bgo[0])));
}

__global__ void mixed_k(const float* __restrict__ loc, const float* __restrict__ glob,
                        const float* __restrict__ alpha,
                        __nv_bfloat16* __restrict__ mh, __nv_bfloat16* __restrict__ ml)
{
    size_t i = (size_t)blockIdx.x*blockDim.x + threadIdx.x;
    if (i >= S1) return;
    float a = alpha[i >> 10];
    float v = a*loc[i] + (1.f-a)*glob[i];
    __nv_bfloat16 h = __float2bfloat16(v);
    mh[i] = h;
    ml[i] = __float2bfloat16(v - __bfloat162float(h));
}

extern "C" void kernel_launch(void* const* d_in, const int* in_sizes, int n_in,
                              void* d_out, int out_size)
{
    const float* x   = (const float*)d_in[0];
    const float* Wq  = (const float*)d_in[1];
    const float* Wk  = (const float*)d_in[2];
    const float* Wv  = (const float*)d_in[3];
    const float* Wkl = (const float*)d_in[4];
    const float* Wvl = (const float*)d_in[5];
    const float* hWk = (const float*)d_in[6];
    const float* hWv = (const float*)d_in[7];
    const float* hsc = (const float*)d_in[8];
    const float* Wg  = (const float*)d_in[9];
    const float* bg  = (const float*)d_in[10];
    const float* Wgo = (const float*)d_in[11];
    const float* bgo = (const float*)d_in[12];
    const float* Wo  = (const float*)d_in[13];
    const float* bo  = (const float*)d_in[14];
    float* out = (float*)d_out;
    (void)in_sizes; (void)n_in; (void)out_size;

    float* S = nullptr;
    cudaGetSymbolAddress((void**)&S, g_scratch);

    cudaFuncSetAttribute(linatt, cudaFuncAttributeMaxDynamicSharedMemorySize, LA_SMEM_BYTES);
    cudaFuncSetAttribute(local_attn, cudaFuncAttributeMaxDynamicSharedMemorySize, LOCAL_SMEM_BYTES);
    cudaFuncSetAttribute(gemm_bf16, cudaFuncAttributeMaxDynamicSharedMemorySize, GEMM_SMEM_BYTES);

    __nv_bfloat16* WB  = (__nv_bfloat16*)(S + OFF_WB);
    __nv_bfloat16* ABh = (__nv_bfloat16*)(S + OFF_AB);
    __nv_bfloat16* ABl = ABh + S1;
    __nv_bfloat16* XDh = (__nv_bfloat16*)(S + OFF_XDB);
    __nv_bfloat16* XDl = XDh + 2*S1;
    __nv_bfloat16* MXh = (__nv_bfloat16*)(S + OFF_MIX);
    __nv_bfloat16* MXl = MXh + S1;

    dim3 blk(256);
    int nb = (int)((S1 + 255)/256);
    dim3 gB(DM/128, N_TOK/128, 1);

    {
        CW cw; cw.src[0]=Wq; cw.src[1]=Wk; cw.src[2]=Wv; cw.src[3]=Wkl; cw.src[4]=Wvl;
        conv_w5<<<dim3(256,1,5), 256>>>(cw, WB);
    }
    {
        size_t c0 = 699051, c1 = 699051, c2 = S1 - c0 - c1;
        conv_bf16<<<512, 256>>>(x,           ABh,           ABl,           c0);
        conv_bf16<<<512, 256>>>(x + c0,      ABh + c0,      ABl + c0,      c1);
        conv_bf16<<<512, 256>>>(x + c0 + c1, ABh + c0 + c1, ABl + c0 + c1, c2);
    }

    // 5 projections; Q/K/V slots also emit phi(Y)/copy (replaces phi_prep)
    {
        PB p;
        for (int w = 0; w < 5; w++){
            p.Wh[w] = WB + (size_t)w*2*DMDM;
            p.Wl[w] = WB + (size_t)w*2*DMDM + DMDM;
            p.b[w]  = nullptr;
            p.Y2[w] = nullptr;
            p.c2[w] = 0;
        }
        p.Y[0]=S+OFF_Q; p.Y[1]=S+OFF_K; p.Y[2]=S+OFF_V; p.Y[3]=S+OFF_KL; p.Y[4]=S+OFF_VL;
        p.Y2[0]=S+OFF_QP; p.c2[0]=2;
        p.Y2[1]=S+OFF_KP; p.c2[1]=2;
        p.Y2[2]=S+OFF_VX; p.c2[2]=3;
        gemm_bf16<<<dim3(DM/128, N_TOK/128, NVAR), 256, GEMM_SMEM_BYTES>>>(ABh, ABl, DM, p, DM, DM, DM, 0);
    }

    // fused haar transform + blockmean + phi, all 4 levels in one launch
    haar_fused<<<dim3(1, N_TOK/64, NLVL*NH*2), blk>>>(S+OFF_K, S+OFF_V, hWk, hWv,
                                                      S+OFF_KP, S+OFF_VX);

    dim3 gA(NCK, NH, NVAR);
    chunk_kv<<<gA, blk>>>(S+OFF_KP, S+OFF_VX, S+OFF_CKV, S+OFF_CK);
    prefix_scan<<<dim3(NH, NVAR), blk>>>(S+OFF_CKV, S+OFF_CK);
    linatt<<<gA, blk, LA_SMEM_BYTES>>>(S+OFF_QP, S+OFF_KP, S+OFF_VX, S+OFF_CKV, S+OFF_CK, S+OFF_OLA);

    local_attn<<<dim3(N_TOK/64, NH), 128, LOCAL_SMEM_BYTES>>>(S+OFF_Q, S+OFF_KL, S+OFF_VL, S+OFF_LOC);

    combine<<<nb, 256>>>(x, hsc, S+OFF_OLA, S+OFF_LOC, S+OFF_GLOB, XDh, XDl);
    conv_bf16<<<1024, 256>>>(Wg, WB, WB + 2*DMDM, 2*DMDM);
    {
        PB p;
        for (int i2=0;i2<5;i2++){ p.Wh[i2]=nullptr; p.Wl[i2]=nullptr; p.b[i2]=nullptr;
                                  p.Y[i2]=nullptr; p.Y2[i2]=nullptr; p.c2[i2]=0; }
        p.Wh[0] = WB; p.Wl[0] = WB + 2*DMDM; p.b[0] = bg; p.Y[0] = S+OFF_GH;
        gemm_bf16<<<gB, 256, GEMM_SMEM_BYTES>>>(XDh, XDl, 2*DM, p, 2*DM, DM, 2*DM, 1);
    }
    alpha_k<<<N_TOK/8, 256>>>(S+OFF_GH, Wgo, bgo, S+OFF_ALPHA);
    mixed_k<<<nb, 256>>>(S+OFF_LOC, S+OFF_GLOB, S+OFF_ALPHA, MXh, MXl);

    conv_bf16<<<1024, 256>>>(Wo, WB, WB + DMDM, DMDM);
    {
        PB p;
        for (int i2=0;i2<5;i2++){ p.Wh[i2]=nullptr; p.Wl[i2]=nullptr; p.b[i2]=nullptr;
                                  p.Y[i2]=nullptr; p.Y2[i2]=nullptr; p.c2[i2]=0; }
        p.Wh[0] = WB; p.Wl[0] = WB + DMDM; p.b[0] = bo; p.Y[0] = out;
        gemm_bf16<<<gB, 256, GEMM_SMEM_BYTES>>>(MXh, MXl, DM, p, DM, DM, DM, 0);
    }
}

// round 16
// speedup vs baseline: 1.0350x; 1.0350x over previous
#include <cuda_runtime.h>
#include <cuda_bf16.h>
#include <math.h>
#include <stdint.h>

#define N_TOK 2048
#define DM    1024
#define NH    16
#define DH    64
#define CHK   128
#define NCK   16
#define NLVL  4
#define NVAR  5
#define S1 ((size_t)N_TOK*DM)
#define DMDM ((size_t)DM*DM)

typedef unsigned long long ull;

__device__ float g_scratch[67108864];  // 256 MB scratch

#define OFF_Q     ((size_t)0)
#define OFF_K     (1*S1)
#define OFF_V     (2*S1)
#define OFF_KL    (3*S1)
#define OFF_VL    (4*S1)
#define OFF_QP    (5*S1)
#define OFF_KP    (6*S1)
#define OFF_VX    (11*S1)
#define OFF_WB    (16*S1)
#define OFF_OLA   (18*S1)
#define OFF_AB    (21*S1)
#define OFF_LOC   (23*S1)
#define OFF_GLOB  (24*S1)
#define OFF_XDB   (25*S1)
#define OFF_GH    (27*S1)
#define OFF_MIX   (28*S1)
#define OFF_CKV   (29*S1)
#define OFF_CK    (OFF_CKV + (size_t)NVAR*NH*NCK*DH*DH)
#define OFF_ALPHA (OFF_CK + (size_t)NVAR*NH*NCK*DH)

__device__ __forceinline__ float phi_f(float x){ return x > 0.f ? x + 1.f : expf(x); }

// ---------- f32x2 packed math ----------
__device__ __forceinline__ ull pk2(float lo, float hi){
    ull r; asm("mov.b64 %0, {%1,%2};" : "=l"(r) : "f"(lo), "f"(hi)); return r;
}
__device__ __forceinline__ void upk2(ull v, float& lo, float& hi){
    asm("mov.b64 {%0,%1}, %2;" : "=f"(lo), "=f"(hi) : "l"(v));
}
__device__ __forceinline__ void fma2(ull& d, ull a, ull b){
    asm("fma.rn.f32x2 %0, %1, %2, %0;" : "+l"(d) : "l"(a), "l"(b));
}

__device__ __forceinline__ uint32_t smem_u32addr(const void* p){
    uint32_t a;
    asm("{ .reg .u64 t; cvta.to.shared.u64 t, %1; cvt.u32.u64 %0, t; }" : "=r"(a) : "l"(p));
    return a;
}
__device__ __forceinline__ void cp_async16(uint32_t saddr, const void* gptr){
    asm volatile("cp.async.cg.shared.global [%0], [%1], 16;" :: "r"(saddr), "l"(gptr));
}

// ===================== f32 -> bf16 hi/lo split =====================
__global__ void conv_bf16(const float* __restrict__ in, __nv_bfloat16* __restrict__ hi,
                          __nv_bfloat16* __restrict__ lo, size_t n)
{
    for (size_t i = (size_t)blockIdx.x*blockDim.x + threadIdx.x; i < n;
         i += (size_t)gridDim.x*blockDim.x){
        float x = in[i];
        __nv_bfloat16 h = __float2bfloat16(x);
        hi[i] = h;
        lo[i] = __float2bfloat16(x - __bfloat162float(h));
    }
}

struct CW { const float* src[5]; };
__global__ void conv_w5(CW cw, __nv_bfloat16* __restrict__ base)
{
    const float* __restrict__ in = cw.src[blockIdx.z];
    __nv_bfloat16* hi = base + (size_t)blockIdx.z*2*DMDM;
    __nv_bfloat16* lo = hi + DMDM;
    for (size_t i = (size_t)blockIdx.x*blockDim.x + threadIdx.x; i < DMDM;
         i += (size_t)gridDim.x*blockDim.x){
        float x = in[i];
        __nv_bfloat16 h = __float2bfloat16(x);
        hi[i] = h;
        lo[i] = __float2bfloat16(x - __bfloat162float(h));
    }
}

// ===================== bf16 split tensor-core GEMM (3-stage cp.async, 2 CTAs/SM) =====================
// per-slot secondary output Y2 with code: 0=none, 2=phi(Y), 3=copy(Y)
struct PB {
    const __nv_bfloat16* Wh[5];
    const __nv_bfloat16* Wl[5];
    const float* b[5];
    float*       Y[5];
    float*       Y2[5];
    int          c2[5];
};

__device__ __forceinline__ void mma_bf16(float* d, const uint32_t* a, const uint32_t* b){
    asm("mma.sync.aligned.m16n8k16.row.col.f32.bf16.bf16.f32 "
        "{%0,%1,%2,%3}, {%4,%5,%6,%7}, {%8,%9}, {%0,%1,%2,%3};"
        : "+f"(d[0]),"+f"(d[1]),"+f"(d[2]),"+f"(d[3])
        : "r"(a[0]),"r"(a[1]),"r"(a[2]),"r"(a[3]),
          "r"(b[0]),"r"(b[1]));
}

#define GS_ROW 12
#define GS_MAT (128*GS_ROW)
#define GS_STAGE (2*GS_MAT)
#define GSTAGES 3
#define GS_HALF (GSTAGES*GS_STAGE)
#define GEMM_SMEM_BYTES (2*GS_HALF*4)       // 73728

__global__ __launch_bounds__(256, 2)
void gemm_bf16(const __nv_bfloat16* __restrict__ Ah, const __nv_bfloat16* __restrict__ Al,
               int lda, PB p, int ldw, int ldy, int K, int act)
{
    extern __shared__ uint32_t gsm[];
    uint32_t* SA = gsm;
    uint32_t* SB = gsm + GS_HALF;

    const __nv_bfloat16* __restrict__ Wh = p.Wh[blockIdx.z];
    const __nv_bfloat16* __restrict__ Wl = p.Wl[blockIdx.z];
    const float* __restrict__ bias       = p.b[blockIdx.z];
    float* __restrict__ Y                = p.Y[blockIdx.z];
    float* __restrict__ Y2               = p.Y2[blockIdx.z];
    const int code                       = p.c2[blockIdx.z];

    const int tid  = threadIdx.x;
    const int lane = tid & 31;
    const int warp = tid >> 5;
    const int wm = warp >> 2;
    const int wn = warp & 3;
    const int g  = lane >> 2;
    const int t4 = lane & 3;
    const int m0 = blockIdx.y * 128, n0 = blockIdx.x * 128;

    const int r   = tid >> 1;
    const int ch  = tid & 1;
    const int c8  = ch * 8;

    const uint32_t sA = smem_u32addr(SA);
    const uint32_t sB = smem_u32addr(SB);

    float acc[4][4][4] = {};

    auto issue = [&](int st, int k0){
        const size_t ao = (size_t)(m0 + r)*lda + k0 + c8;
        const size_t bo = (size_t)(n0 + r)*ldw + k0 + c8;
        uint32_t off = ((uint32_t)st*GS_STAGE + (uint32_t)r*GS_ROW + ch*4)*4;
        cp_async16(sA + off,              Ah + ao);
        cp_async16(sA + off + GS_MAT*4,   Al + ao);
        cp_async16(sB + off,              Wh + bo);
        cp_async16(sB + off + GS_MAT*4,   Wl + bo);
    };

    const int nsteps = K >> 4;
    issue(0, 0);
    asm volatile("cp.async.commit_group;");
    issue(1, 16);
    asm volatile("cp.async.commit_group;");

    for (int s = 0; s < nsteps; s++){
        const bool more2 = (s + 2 < nsteps);
        if (more2) asm volatile("cp.async.wait_group 1;");
        else       asm volatile("cp.async.wait_group 0;");
        __syncthreads();
        const int st = s % GSTAGES;
        if (more2){
            issue((s + 2) % GSTAGES, (s + 2) * 16);
            asm volatile("cp.async.commit_group;");
        }
        const uint32_t* Acur = SA + st*GS_STAGE;
        const uint32_t* Bcur = SB + st*GS_STAGE;
        uint32_t bh[4][2], bl[4][2];
        #pragma unroll
        for (int j = 0; j < 4; j++){
            int nb = wn*32 + j*8 + g;
            bh[j][0] = Bcur[nb*GS_ROW + t4];
            bh[j][1] = Bcur[nb*GS_ROW + t4 + 4];
            bl[j][0] = Bcur[GS_MAT + nb*GS_ROW + t4];
            bl[j][1] = Bcur[GS_MAT + nb*GS_ROW + t4 + 4];
        }
        #pragma unroll
        for (int i = 0; i < 4; i++){
            int mb = wm*64 + i*16 + g;
            uint32_t a_h[4], a_l[4];
            a_h[0] = Acur[mb*GS_ROW + t4];
            a_h[1] = Acur[(mb+8)*GS_ROW + t4];
            a_h[2] = Acur[mb*GS_ROW + t4 + 4];
            a_h[3] = Acur[(mb+8)*GS_ROW + t4 + 4];
            a_l[0] = Acur[GS_MAT + mb*GS_ROW + t4];
            a_l[1] = Acur[GS_MAT + (mb+8)*GS_ROW + t4];
            a_l[2] = Acur[GS_MAT + mb*GS_ROW + t4 + 4];
            a_l[3] = Acur[GS_MAT + (mb+8)*GS_ROW + t4 + 4];
            #pragma unroll
            for (int j = 0; j < 4; j++){
                mma_bf16(acc[i][j], a_h, bh[j]);
                mma_bf16(acc[i][j], a_h, bl[j]);
                mma_bf16(acc[i][j], a_l, bh[j]);
            }
        }
        __syncthreads();
    }

    #pragma unroll
    for (int i = 0; i < 4; i++){
        int mrow = m0 + wm*64 + i*16 + g;
        #pragma unroll
        for (int j = 0; j < 4; j++){
            int ncol = n0 + wn*32 + j*8 + 2*t4;
            float v0 = acc[i][j][0], v1 = acc[i][j][1];
            float v2 = acc[i][j][2], v3 = acc[i][j][3];
            if (bias){
                float b0 = bias[ncol], b1 = bias[ncol+1];
                v0 += b0; v1 += b1; v2 += b0; v3 += b1;
            }
            if (act == 1){
                v0 = v0/(1.f+expf(-v0)); v1 = v1/(1.f+expf(-v1));
                v2 = v2/(1.f+expf(-v2)); v3 = v3/(1.f+expf(-v3));
            }
            float2 o01; o01.x = v0; o01.y = v1;
            float2 o23; o23.x = v2; o23.y = v3;
            *reinterpret_cast<float2*>(&Y[(size_t)mrow*ldy + ncol])     = o01;
            *reinterpret_cast<float2*>(&Y[(size_t)(mrow+8)*ldy + ncol]) = o23;
            if (code){
                float w0=v0, w1=v1, w2=v2, w3=v3;
                if (code == 2){ w0=phi_f(v0); w1=phi_f(v1); w2=phi_f(v2); w3=phi_f(v3); }
                float2 p01; p01.x = w0; p01.y = w1;
                float2 p23; p23.x = w2; p23.y = w3;
                *reinterpret_cast<float2*>(&Y2[(size_t)mrow*ldy + ncol])     = p01;
                *reinterpret_cast<float2*>(&Y2[(size_t)(mrow+8)*ldy + ncol]) = p23;
            }
        }
    }
}

// ===================== fused haar transform + causal blockmean + phi =====================
__global__ void haar_fused(const float* __restrict__ Kin, const float* __restrict__ Vin,
                           const float* __restrict__ hWk, const float* __restrict__ hWv,
                           float* __restrict__ kd_base, float* __restrict__ vd_base)
{
    __shared__ __align__(16) float As[16][68];
    __shared__ __align__(16) float Ws[16][68];
    __shared__ __align__(16) float Ys[64][68];
    const int z = blockIdx.z;
    const int lvl = z >> 5;
    const int h  = (z >> 1) & 15;
    const int kv = z & 1;
    const int blkm = 2 << lvl;
    const float* A = (kv ? Vin : Kin) + h*DH;
    const float* W = (kv ? hWv : hWk) + (size_t)lvl*DH*DH;
    float* Yout = (kv ? vd_base : kd_base) + (size_t)(lvl+1)*S1 + h*DH;
    const int t  = threadIdx.x;
    const int tx = t & 15, ty = t >> 4;
    const int m0 = blockIdx.y * 64;
    const int lrow = t >> 2;
    const int lk   = (t & 3) * 4;
    float acc[4][4] = {};
    for (int k0 = 0; k0 < DH; k0 += 16) {
        float4 av = *reinterpret_cast<const float4*>(&A[(size_t)(m0 + lrow)*DM + k0 + lk]);
        float4 wv = *reinterpret_cast<const float4*>(&W[(size_t)lrow*DH + k0 + lk]);
        As[lk+0][lrow]=av.x; As[lk+1][lrow]=av.y; As[lk+2][lrow]=av.z; As[lk+3][lrow]=av.w;
        Ws[lk+0][lrow]=wv.x; Ws[lk+1][lrow]=wv.y; Ws[lk+2][lrow]=wv.z; Ws[lk+3][lrow]=wv.w;
        __syncthreads();
        #pragma unroll
        for (int kk = 0; kk < 16; kk++) {
            float4 a = *reinterpret_cast<float4*>(&As[kk][ty*4]);
            float4 b = *reinterpret_cast<float4*>(&Ws[kk][tx*4]);
            float aa[4] = {a.x,a.y,a.z,a.w};
            float bb[4] = {b.x,b.y,b.z,b.w};
            #pragma unroll
            for (int i=0;i<4;i++)
                #pragma unroll
                for (int j=0;j<4;j++)
                    acc[i][j] += aa[i]*bb[j];
        }
        __syncthreads();
    }
    #pragma unroll
    for (int i=0;i<4;i++){
        float4 o; o.x=acc[i][0]; o.y=acc[i][1]; o.z=acc[i][2]; o.w=acc[i][3];
        *reinterpret_cast<float4*>(&Ys[ty*4+i][tx*4]) = o;
    }
    __syncthreads();
    {
        const int c = t & 63;
        const int r0 = (t >> 6) * 16;
        const int mask = blkm - 1;
        float run = 0.f;
        #pragma unroll
        for (int rr = 0; rr < 16; rr++){
            int m = r0 + rr;
            if ((m & mask) == 0) run = 0.f;
            run += Ys[m][c];
            float inv = 1.0f / (float)((m & mask) + 1);
            float val = run * inv;
            if (!kv) val = phi_f(val);
            Yout[(size_t)(m0 + m)*DM + c] = val;
        }
    }
}

// phase A: ckv = Kc^T Vc, ck = colsum(Kc)  (f32x2 inner loop)
__global__ void chunk_kv(const float* __restrict__ kp, const float* __restrict__ vx,
                         float* __restrict__ ckv, float* __restrict__ ck)
{
    __shared__ __align__(16) float Ks[16][68], Vs[16][68];
    const int c = blockIdx.x, h = blockIdx.y, vv = blockIdx.z;
    const int t = threadIdx.x, tx = t & 15, ty = t >> 4;
    const float* kb = kp + (size_t)vv*S1;
    const float* vb = vx + (size_t)vv*S1;
    const size_t rowbase = (size_t)c*CHK*DM + (size_t)h*DH;
    const int lr = t >> 4, lc = (t & 15) * 4;
    ull acc2[4][2] = {};
    for (int k0 = 0; k0 < CHK; k0 += 16){
        float4 a = *reinterpret_cast<const float4*>(&kb[rowbase + (size_t)(k0+lr)*DM + lc]);
        float4 b = *reinterpret_cast<const float4*>(&vb[rowbase + (size_t)(k0+lr)*DM + lc]);
        Ks[lr][lc+0]=a.x; Ks[lr][lc+1]=a.y; Ks[lr][lc+2]=a.z; Ks[lr][lc+3]=a.w;
        Vs[lr][lc+0]=b.x; Vs[lr][lc+1]=b.y; Vs[lr][lc+2]=b.z; Vs[lr][lc+3]=b.w;
        __syncthreads();
        #pragma unroll
        for (int kk = 0; kk < 16; kk++){
            float4 a4 = *reinterpret_cast<float4*>(&Ks[kk][ty*4]);
            ull b2a = *reinterpret_cast<ull*>(&Vs[kk][tx*4]);
            ull b2b = *reinterpret_cast<ull*>(&Vs[kk][tx*4+2]);
            float aa[4]={a4.x,a4.y,a4.z,a4.w};
            #pragma unroll
            for (int i=0;i<4;i++){
                ull ai = pk2(aa[i], aa[i]);
                fma2(acc2[i][0], ai, b2a);
                fma2(acc2[i][1], ai, b2b);
            }
        }
        __syncthreads();
    }
    float* outm = ckv + (((size_t)vv*NH + h)*NCK + c)*((size_t)DH*DH);
    #pragma unroll
    for (int i=0;i<4;i++){
        float o0,o1,o2,o3;
        upk2(acc2[i][0], o0, o1);
        upk2(acc2[i][1], o2, o3);
        float4 o; o.x=o0; o.y=o1; o.z=o2; o.w=o3;
        *reinterpret_cast<float4*>(&outm[(size_t)(ty*4+i)*DH + tx*4]) = o;
    }
    if (t < DH){
        float s = 0.f;
        for (int r = 0; r < CHK; r++) s += kb[rowbase + (size_t)r*DM + t];
        ck[(((size_t)vv*NH + h)*NCK + c)*DH + t] = s;
    }
}

// phase B: exclusive prefix over chunks
__global__ void prefix_scan(float* __restrict__ ckv, float* __restrict__ ck)
{
    const int h = blockIdx.x, vv = blockIdx.y, t = threadIdx.x;
    const size_t base = (((size_t)vv*NH + h)*NCK) * (size_t)(DH*DH);
    for (int u = t; u < DH*DH; u += 256){
        float run = 0.f;
        for (int c = 0; c < NCK; c++){
            size_t idx = base + (size_t)c*DH*DH + u;
            float tmp = ckv[idx]; ckv[idx] = run; run += tmp;
        }
    }
    if (t < DH){
        const size_t b2 = (((size_t)vv*NH + h)*NCK) * (size_t)DH;
        float run = 0.f;
        for (int c = 0; c < NCK; c++){
            size_t idx = b2 + (size_t)c*DH + t;
            float tmp = ck[idx]; ck[idx] = run; run += tmp;
        }
    }
}

// phase C with f32x2 packed FMA
#define LA_SMEM_FLOATS (64*132 + 128*68 + 128*132 + 64*68 + 64 + 128)
#define LA_SMEM_BYTES  (LA_SMEM_FLOATS*4)
__global__ void linatt(const float* __restrict__ qp, const float* __restrict__ kp,
                       const float* __restrict__ vx, const float* __restrict__ ckv,
                       const float* __restrict__ ck, float* __restrict__ ola)
{
    extern __shared__ float sm[];
    const int c = blockIdx.x, h = blockIdx.y, vv = blockIdx.z;
    const int t = threadIdx.x, tx = t & 15, ty = t >> 4;
    float* Qt   = sm;
    float* KVu  = Qt + 64*132;
    float* Ss   = KVu + 128*68;
    float* SKVs = Ss + 128*132;
    float* SKs  = SKVs + 64*68;
    float* nrm  = SKs + 64;
    const float* kb = kp + (size_t)vv*S1;
    const float* vb = vx + (size_t)vv*S1;
    const size_t rowbase = (size_t)c*CHK*DM + (size_t)h*DH;
    {
        int d = t & 63;
        for (int g = t >> 6; g < CHK; g += 4){
            Qt[d*132 + g]  = qp[rowbase + (size_t)g*DM + d];
            KVu[d*132 + g] = kb[rowbase + (size_t)g*DM + d];
        }
    }
    __syncthreads();
    {
        ull acc2[8][4] = {};
        #pragma unroll 2
        for (int d = 0; d < DH; d++){
            float4 a0 = *reinterpret_cast<float4*>(&Qt[d*132 + ty*8]);
            float4 a1 = *reinterpret_cast<float4*>(&Qt[d*132 + ty*8 + 4]);
            float qa[8]={a0.x,a0.y,a0.z,a0.w,a1.x,a1.y,a1.z,a1.w};
            ull qa2[8];
            #pragma unroll
            for (int i=0;i<8;i++) qa2[i] = pk2(qa[i], qa[i]);
            ull kv2[4];
            #pragma unroll
            for (int j2=0;j2<4;j2++)
                kv2[j2] = *reinterpret_cast<ull*>(&KVu[d*132 + tx*8 + 2*j2]);
            #pragma unroll
            for (int i=0;i<8;i++)
                #pragma unroll
                for (int j2=0;j2<4;j2++)
                    fma2(acc2[i][j2], qa2[i], kv2[j2]);
        }
        #pragma unroll
        for (int i=0;i<8;i++){
            int gi = ty*8+i;
            #pragma unroll
            for (int j2=0;j2<4;j2++){
                float slo, shi; upk2(acc2[i][j2], slo, shi);
                int gj = tx*8 + 2*j2;
                float2 st;
                st.x = (gj   <= gi) ? slo : 0.0f;
                st.y = (gj+1 <= gi) ? shi : 0.0f;
                *reinterpret_cast<float2*>(&Ss[gi*132+gj]) = st;
            }
        }
    }
    __syncthreads();
    {
        int d = t & 63;
        for (int g = t >> 6; g < CHK; g += 4)
            KVu[g*68 + d] = vb[rowbase + (size_t)g*DM + d];
        const float* mc = ckv + (((size_t)vv*NH + h)*NCK + c)*((size_t)DH*DH);
        for (int u = t; u < DH*DH; u += 256)
            SKVs[(u>>6)*68 + (u&63)] = mc[u];
        if (t < DH) SKs[t] = ck[(((size_t)vv*NH + h)*NCK + c)*DH + t];
    }
    __syncthreads();
    if (t < CHK){
        float s = 0.f;
        for (int j = 0; j < CHK; j++) s += Ss[t*132 + j];
        float s2 = 0.f;
        for (int d = 0; d < DH; d++) s2 += Qt[d*132 + t]*SKs[d];
        nrm[t] = fmaxf(s + s2, 1e-6f);
    }
    __syncthreads();
    ull outv2[8][2] = {};
    #pragma unroll 2
    for (int d = 0; d < DH; d++){
        float4 a0 = *reinterpret_cast<float4*>(&Qt[d*132 + ty*8]);
        float4 a1 = *reinterpret_cast<float4*>(&Qt[d*132 + ty*8 + 4]);
        float qa[8]={a0.x,a0.y,a0.z,a0.w,a1.x,a1.y,a1.z,a1.w};
        ull qa2[8];
        #pragma unroll
        for (int i=0;i<8;i++) qa2[i] = pk2(qa[i], qa[i]);
        ull bb2[2];
        bb2[0] = *reinterpret_cast<ull*>(&SKVs[d*68 + tx*4]);
        bb2[1] = *reinterpret_cast<ull*>(&SKVs[d*68 + tx*4 + 2]);
        #pragma unroll
        for (int i=0;i<8;i++){
            fma2(outv2[i][0], qa2[i], bb2[0]);
            fma2(outv2[i][1], qa2[i], bb2[1]);
        }
    }
    #pragma unroll 2
    for (int kk = 0; kk < CHK; kk++){
        ull vb2[2];
        vb2[0] = *reinterpret_cast<ull*>(&KVu[kk*68 + tx*4]);
        vb2[1] = *reinterpret_cast<ull*>(&KVu[kk*68 + tx*4 + 2]);
        #pragma unroll
        for (int i=0;i<8;i++){
            float sv = Ss[(ty*8+i)*132 + kk];
            ull sv2 = pk2(sv, sv);
            fma2(outv2[i][0], sv2, vb2[0]);
            fma2(outv2[i][1], sv2, vb2[1]);
        }
    }
    float* ob = ola + (size_t)vv*S1;
    #pragma unroll
    for (int i=0;i<8;i++){
        int gi = ty*8+i;
        float inv = 1.0f / nrm[gi];
        float o0,o1,o2,o3;
        upk2(outv2[i][0], o0, o1);
        upk2(outv2[i][1], o2, o3);
        float4 o; o.x=o0*inv; o.y=o1*inv; o.z=o2*inv; o.w=o3*inv;
        *reinterpret_cast<float4*>(&ob[(size_t)(c*CHK+gi)*DM + h*DH + tx*4]) = o;
    }
}

// local windowed attention (window 64, causal): 64 threads, 1 per query, cached scores.
#define LOCAL_SMEM_BYTES ((2*128*68 + 64*65)*4)
__global__ void local_attn(const float* __restrict__ q, const float* __restrict__ kl,
                           const float* __restrict__ vl, float* __restrict__ outp)
{
    extern __shared__ float sm[];
    float* kT  = sm;                // [128][68]
    float* vT  = sm + 128*68;       // [128][68]
    float* scS = sm + 2*128*68;     // [64][65]
    const int h = blockIdx.y;
    const int qstart = blockIdx.x * 64;
    const int t = threadIdx.x;      // 0..63
    for (int g = 0; g < 128; g++){
        int gk = qstart - 64 + g;
        float kv = 0.f, vv = 0.f;
        if (gk >= 0){
            kv = kl[(size_t)gk*DM + h*DH + t];
            vv = vl[(size_t)gk*DM + h*DH + t];
        }
        kT[g*68 + t] = kv;
        vT[g*68 + t] = vv;
    }
    __syncthreads();
    const int i = qstart + t;
    ull qr2[32];
    #pragma unroll
    for (int d2 = 0; d2 < 32; d2++)
        qr2[d2] = *reinterpret_cast<const ull*>(&q[(size_t)i*DM + h*DH + 2*d2]);
    const float scale = 0.125f;
    int nj = min(64, i + 1);
    float m = -1e30f;
    for (int j = 0; j < nj; j++){
        int r = t - j + 64;
        ull sa=0, sb=0, sc=0, sd=0;
        #pragma unroll
        for (int d2 = 0; d2 < 32; d2 += 4){
            fma2(sa, qr2[d2  ], *reinterpret_cast<ull*>(&kT[r*68 + 2*d2    ]));
            fma2(sb, qr2[d2+1], *reinterpret_cast<ull*>(&kT[r*68 + 2*d2 + 2]));
            fma2(sc, qr2[d2+2], *reinterpret_cast<ull*>(&kT[r*68 + 2*d2 + 4]));
            fma2(sd, qr2[d2+3], *reinterpret_cast<ull*>(&kT[r*68 + 2*d2 + 6]));
        }
        float a0,a1,b0,b1,c0,c1,d0,d1;
        upk2(sa,a0,a1); upk2(sb,b0,b1); upk2(sc,c0,c1); upk2(sd,d0,d1);
        float s = ((a0+a1)+(b0+b1)) + ((c0+c1)+(d0+d1));
        scS[t*65 + j] = s;
        m = fmaxf(m, s*scale);
    }
    float l = 0.f;
    ull accv2[32] = {};
    for (int j = 0; j < nj; j++){
        int r = t - j + 64;
        float w = expf(scS[t*65 + j]*scale - m);
        l += w;
        ull w2 = pk2(w, w);
        #pragma unroll
        for (int e2 = 0; e2 < 32; e2++)
            fma2(accv2[e2], w2, *reinterpret_cast<ull*>(&vT[r*68 + 2*e2]));
    }
    float inv = 1.f / l;
    #pragma unroll
    for (int e2 = 0; e2 < 32; e2++){
        float lo, hi; upk2(accv2[e2], lo, hi);
        float2 o; o.x = lo*inv; o.y = hi*inv;
        *reinterpret_cast<float2*>(&outp[(size_t)i*DM + h*DH + 2*e2]) = o;
    }
}

// glob + xd (bf16 hi/lo, own region — no aliasing)
__global__ void combine(const float* __restrict__ x, const float* __restrict__ hsc,
                        const float* __restrict__ ola, const float* __restrict__ loc,
                        float* __restrict__ glob,
                        __nv_bfloat16* __restrict__ xdh, __nv_bfloat16* __restrict__ xdl)
{
    size_t i = (size_t)blockIdx.x*blockDim.x + threadIdx.x;
    if (i >= S1) return;
    float hs[NLVL], m = -1e30f;
    #pragma unroll
    for (int l = 0; l < NLVL; l++){ hs[l] = hsc[l]; m = fmaxf(m, hs[l]); }
    float ssum = 0.f, w[NLVL];
    #pragma unroll
    for (int l = 0; l < NLVL; l++){ w[l] = expf(hs[l]-m); ssum += w[l]; }
    float inv = 1.f/ssum;
    float g = ola[i];
    #pragma unroll
    for (int l = 0; l < NLVL; l++) g += (w[l]*inv) * ola[(size_t)(l+1)*S1 + i];
    glob[i] = g;
    size_t n = i >> 10, d = i & 1023;
    float v1 = x[i];
    __nv_bfloat16 h1 = __float2bfloat16(v1);
    xdh[n*2048 + d] = h1;
    xdl[n*2048 + d] = __float2bfloat16(v1 - __bfloat162float(h1));
    float v2 = loc[i] - g;
    __nv_bfloat16 h2 = __float2bfloat16(v2);
    xdh[n*2048 + 1024 + d] = h2;
    xdl[n*2048 + 1024 + d] = __float2bfloat16(v2 - __bfloat162float(h2));
}

__global__ void alpha_k(const float* __restrict__ gh, const float* __restrict__ Wgo,
                        const float* __restrict__ bgo, float* __restrict__ alpha)
{
    int warp = threadIdx.x >> 5, lane = threadIdx.x & 31;
    int row = blockIdx.x*8 + warp;
    if (row >= N_TOK) return;
    float s = 0.f;
    for (int kk = lane; kk < DM; kk += 32) s += gh[(size_t)row*DM + kk]*Wgo[kk];
    #pragma unroll
    for (int o = 16; o; o >>= 1) s += __shfl_xor_sync(0xffffffffu, s, o);
    if (lane == 0) alpha[row] = 1.f/(1.f + expf(-(s + bgo[0])));
}

__global__ void mixed_k(const float* __restrict__ loc, const float* __restrict__ glob,
                        const float* __restrict__ alpha,
                        __nv_bfloat16* __restrict__ mh, __nv_bfloat16* __restrict__ ml)
{
    size_t i = (size_t)blockIdx.x*blockDim.x + threadIdx.x;
    if (i >= S1) return;
    float a = alpha[i >> 10];
    float v = a*loc[i] + (1.f-a)*glob[i];
    __nv_bfloat16 h = __float2bfloat16(v);
    mh[i] = h;
    ml[i] = __float2bfloat16(v - __bfloat162float(h));
}

extern "C" void kernel_launch(void* const* d_in, const int* in_sizes, int n_in,
                              void* d_out, int out_size)
{
    const float* x   = (const float*)d_in[0];
    const float* Wq  = (const float*)d_in[1];
    const float* Wk  = (const float*)d_in[2];
    const float* Wv  = (const float*)d_in[3];
    const float* Wkl = (const float*)d_in[4];
    const float* Wvl = (const float*)d_in[5];
    const float* hWk = (const float*)d_in[6];
    const float* hWv = (const float*)d_in[7];
    const float* hsc = (const float*)d_in[8];
    const float* Wg  = (const float*)d_in[9];
    const float* bg  = (const float*)d_in[10];
    const float* Wgo = (const float*)d_in[11];
    const float* bgo = (const float*)d_in[12];
    const float* Wo  = (const float*)d_in[13];
    const float* bo  = (const float*)d_in[14];
    float* out = (float*)d_out;
    (void)in_sizes; (void)n_in; (void)out_size;

    float* S = nullptr;
    cudaGetSymbolAddress((void**)&S, g_scratch);

    cudaFuncSetAttribute(linatt, cudaFuncAttributeMaxDynamicSharedMemorySize, LA_SMEM_BYTES);
    cudaFuncSetAttribute(local_attn, cudaFuncAttributeMaxDynamicSharedMemorySize, LOCAL_SMEM_BYTES);
    cudaFuncSetAttribute(gemm_bf16, cudaFuncAttributeMaxDynamicSharedMemorySize, GEMM_SMEM_BYTES);

    __nv_bfloat16* WB  = (__nv_bfloat16*)(S + OFF_WB);
    __nv_bfloat16* ABh = (__nv_bfloat16*)(S + OFF_AB);
    __nv_bfloat16* ABl = ABh + S1;
    __nv_bfloat16* XDh = (__nv_bfloat16*)(S + OFF_XDB);
    __nv_bfloat16* XDl = XDh + 2*S1;
    __nv_bfloat16* MXh = (__nv_bfloat16*)(S + OFF_MIX);
    __nv_bfloat16* MXl = MXh + S1;

    dim3 blk(256);
    int nb = (int)((S1 + 255)/256);
    dim3 gB(DM/128, N_TOK/128, 1);

    {
        CW cw; cw.src[0]=Wq; cw.src[1]=Wk; cw.src[2]=Wv; cw.src[3]=Wkl; cw.src[4]=Wvl;
        conv_w5<<<dim3(256,1,5), 256>>>(cw, WB);
    }
    {
        size_t c0 = 699051, c1 = 699051, c2 = S1 - c0 - c1;
        conv_bf16<<<512, 256>>>(x,           ABh,           ABl,           c0);
        conv_bf16<<<512, 256>>>(x + c0,      ABh + c0,      ABl + c0,      c1);
        conv_bf16<<<512, 256>>>(x + c0 + c1, ABh + c0 + c1, ABl + c0 + c1, c2);
    }

    // 5 projections; Q/K/V slots also emit phi(Y)/copy (replaces phi_prep)
    {
        PB p;
        for (int w = 0; w < 5; w++){
            p.Wh[w] = WB + (size_t)w*2*DMDM;
            p.Wl[w] = WB + (size_t)w*2*DMDM + DMDM;
            p.b[w]  = nullptr;
            p.Y2[w] = nullptr;
            p.c2[w] = 0;
        }
        p.Y[0]=S+OFF_Q; p.Y[1]=S+OFF_K; p.Y[2]=S+OFF_V; p.Y[3]=S+OFF_KL; p.Y[4]=S+OFF_VL;
        p.Y2[0]=S+OFF_QP; p.c2[0]=2;
        p.Y2[1]=S+OFF_KP; p.c2[1]=2;
        p.Y2[2]=S+OFF_VX; p.c2[2]=3;
        gemm_bf16<<<dim3(DM/128, N_TOK/128, NVAR), 256, GEMM_SMEM_BYTES>>>(ABh, ABl, DM, p, DM, DM, DM, 0);
    }

    // fused haar transform + blockmean + phi, all 4 levels in one launch
    haar_fused<<<dim3(1, N_TOK/64, NLVL*NH*2), blk>>>(S+OFF_K, S+OFF_V, hWk, hWv,
                                                      S+OFF_KP, S+OFF_VX);

    dim3 gA(NCK, NH, NVAR);
    chunk_kv<<<gA, blk>>>(S+OFF_KP, S+OFF_VX, S+OFF_CKV, S+OFF_CK);
    prefix_scan<<<dim3(NH, NVAR), blk>>>(S+OFF_CKV, S+OFF_CK);
    linatt<<<gA, blk, LA_SMEM_BYTES>>>(S+OFF_QP, S+OFF_KP, S+OFF_VX, S+OFF_CKV, S+OFF_CK, S+OFF_OLA);

    local_attn<<<dim3(N_TOK/64, NH), 64, LOCAL_SMEM_BYTES>>>(S+OFF_Q, S+OFF_KL, S+OFF_VL, S+OFF_LOC);

    combine<<<nb, 256>>>(x, hsc, S+OFF_OLA, S+OFF_LOC, S+OFF_GLOB, XDh, XDl);
    conv_bf16<<<1024, 256>>>(Wg, WB, WB + 2*DMDM, 2*DMDM);
    {
        PB p;
        for (int i2=0;i2<5;i2++){ p.Wh[i2]=nullptr; p.Wl[i2]=nullptr; p.b[i2]=nullptr;
                                  p.Y[i2]=nullptr; p.Y2[i2]=nullptr; p.c2[i2]=0; }
        p.Wh[0] = WB; p.Wl[0] = WB + 2*DMDM; p.b[0] = bg; p.Y[0] = S+OFF_GH;
        gemm_bf16<<<gB, 256, GEMM_SMEM_BYTES>>>(XDh, XDl, 2*DM, p, 2*DM, DM, 2*DM, 1);
    }
    alpha_k<<<N_TOK/8, 256>>>(S+OFF_GH, Wgo, bgo, S+OFF_ALPHA);
    mixed_k<<<nb, 256>>>(S+OFF_LOC, S+OFF_GLOB, S+OFF_ALPHA, MXh, MXl);

    conv_bf16<<<1024, 256>>>(Wo, WB, WB + DMDM, DMDM);
    {
        PB p;
        for (int i2=0;i2<5;i2++){ p.Wh[i2]=nullptr; p.Wl[i2]=nullptr; p.b[i2]=nullptr;
                                  p.Y[i2]=nullptr; p.Y2[i2]=nullptr; p.c2[i2]=0; }
        p.Wh[0] = WB; p.Wl[0] = WB + DMDM; p.b[0] = bo; p.Y[0] = out;
        gemm_bf16<<<gB, 256, GEMM_SMEM_BYTES>>>(MXh, MXl, DM, p, DM, DM, DM, 0);
    }
}